// round 2
// baseline (speedup 1.0000x reference)
#include <cuda_runtime.h>
#include <cuda_bf16.h>
#include <cstdint>

#define NB   16
#define NN   4096
#define NS   1024
#define NK   32
#define NC   64
#define NOUT 128
#define CIN  67          // 3 + 64

// kNN index scratch (static device global; allocation is forbidden)
__device__ int g_idx[NB * NS * NK];

// ---------------------------------------------------------------------------
// Stage 1: farthest point sampling. One block per batch, 1024 threads,
// 4 points/thread register-resident. Emits new_xyz[b][it] directly.
// ---------------------------------------------------------------------------
__global__ __launch_bounds__(1024, 1)
void fps_kernel(const float* __restrict__ xyz, float* __restrict__ new_xyz)
{
    extern __shared__ float sm[];
    float* xs = sm;
    float* ys = sm + NN;
    float* zs = sm + 2 * NN;
    __shared__ unsigned long long wkey[32];
    __shared__ int s_far;

    const int b   = blockIdx.x;
    const int tid = threadIdx.x;
    const int lane = tid & 31, wid = tid >> 5;

    const float* gx = xyz + (size_t)b * NN * 3;
    for (int j = tid; j < NN * 3; j += 1024) {
        float v = gx[j];
        int p = j / 3, c = j - p * 3;
        if (c == 0) xs[p] = v; else if (c == 1) ys[p] = v; else zs[p] = v;
    }
    if (tid == 0) s_far = 0;
    __syncthreads();

    const int base = tid * 4;
    float px[4], py[4], pz[4], dd[4];
#pragma unroll
    for (int j = 0; j < 4; j++) {
        px[j] = xs[base + j]; py[j] = ys[base + j]; pz[j] = zs[base + j];
        dd[j] = 1e10f;
    }

    for (int it = 0; it < NS; it++) {
        const int far = s_far;
        const float cx = xs[far], cy = ys[far], cz = zs[far];
        if (tid == 0) {
            float* o = new_xyz + ((size_t)b * NS + it) * 3;
            o[0] = cx; o[1] = cy; o[2] = cz;
        }
        unsigned long long bk = 0ull;
#pragma unroll
        for (int j = 0; j < 4; j++) {
            float dx = __fsub_rn(px[j], cx);
            float dy = __fsub_rn(py[j], cy);
            float dz = __fsub_rn(pz[j], cz);
            float d  = __fadd_rn(__fadd_rn(__fmul_rn(dx, dx), __fmul_rn(dy, dy)),
                                 __fmul_rn(dz, dz));
            float nd = fminf(dd[j], d);
            dd[j] = nd;
            unsigned long long key =
                ((unsigned long long)__float_as_uint(nd) << 32) |
                (unsigned)(NN - 1 - (base + j));
            bk = (key > bk) ? key : bk;
        }
#pragma unroll
        for (int off = 16; off; off >>= 1) {
            unsigned long long o = __shfl_down_sync(0xffffffffu, bk, off);
            bk = (o > bk) ? o : bk;
        }
        if (lane == 0) wkey[wid] = bk;
        __syncthreads();
        if (wid == 0) {
            unsigned long long k2 = wkey[lane];
#pragma unroll
            for (int off = 16; off; off >>= 1) {
                unsigned long long o = __shfl_down_sync(0xffffffffu, k2, off);
                k2 = (o > k2) ? o : k2;
            }
            if (lane == 0) s_far = NN - 1 - (int)(k2 & 0xffffffffu);
        }
        __syncthreads();
    }
}

// ---------------------------------------------------------------------------
// Stage 2: kNN. One thread per query; candidates (x,y,z,|p|^2) in smem.
// Register-resident unsorted top-32, stable (top_k) tie semantics.
// ---------------------------------------------------------------------------
__global__ __launch_bounds__(128, 4)
void knn_kernel(const float* __restrict__ xyz, const float* __restrict__ new_xyz)
{
    extern __shared__ float4 cand[];           // NN entries = 64 KB
    const int b     = blockIdx.x >> 3;         // 8 blocks of 128 queries per batch
    const int chunk = blockIdx.x & 7;
    const int tid   = threadIdx.x;

    const float* gx = xyz + (size_t)b * NN * 3;
    for (int p = tid; p < NN; p += 128) {
        float x = gx[p * 3], y = gx[p * 3 + 1], z = gx[p * 3 + 2];
        float psq = __fadd_rn(__fadd_rn(__fmul_rn(x, x), __fmul_rn(y, y)),
                              __fmul_rn(z, z));
        cand[p] = make_float4(x, y, z, psq);
    }
    __syncthreads();

    const int s = chunk * 128 + tid;
    const float* q = new_xyz + ((size_t)b * NS + s) * 3;
    const float qx = q[0], qy = q[1], qz = q[2];
    const float qsq = __fadd_rn(__fadd_rn(__fmul_rn(qx, qx), __fmul_rn(qy, qy)),
                                __fmul_rn(qz, qz));

    const float INF = __int_as_float(0x7f800000);
    float nd[NK]; int ni[NK];
#pragma unroll
    for (int t = 0; t < NK; t++) { nd[t] = INF; ni[t] = 0x7fffffff; }
    float wd = INF; int wslot = 0;

    for (int j = 0; j < NN; j++) {
        float4 c = cand[j];
        float dot = __fadd_rn(__fadd_rn(__fmul_rn(qx, c.x), __fmul_rn(qy, c.y)),
                              __fmul_rn(qz, c.z));
        float sq = __fsub_rn(__fadd_rn(qsq, c.w), __fmul_rn(2.0f, dot));
        if (sq < wd) {   // strict: equal value keeps earlier (lower) index, like top_k
#pragma unroll
            for (int t = 0; t < NK; t++)
                if (t == wslot) { nd[t] = sq; ni[t] = j; }
            // rescan for new worst: max dist, tie -> larger index (evicted next)
            float bw = nd[0]; int bwi = ni[0]; int bslot = 0;
#pragma unroll
            for (int t = 1; t < NK; t++) {
                bool g = (nd[t] > bw) || (nd[t] == bw && ni[t] > bwi);
                if (g) { bw = nd[t]; bwi = ni[t]; bslot = t; }
            }
            wd = bw; wslot = bslot;
        }
    }

    int* outp = g_idx + ((size_t)b * NS + s) * NK;
#pragma unroll
    for (int t = 0; t < NK; t++) outp[t] = ni[t];
}

// ---------------------------------------------------------------------------
// Stage 3: gather + 1x1 conv (67->128) + max over K + LayerNorm.
// Thread = output channel; feat tile (32 x 68, padded) in smem; w in regs.
// Slot map: 0..2 = xyz_norm, 3 = pad(0), 4+j = voxels[j]  (keeps float4 align)
// ---------------------------------------------------------------------------
#define QPB 8
__global__ __launch_bounds__(128, 8)
void embed_kernel(const float* __restrict__ xyz, const float* __restrict__ voxels,
                  const float* __restrict__ w, const float* __restrict__ bias,
                  const float* __restrict__ gamma, const float* __restrict__ beta,
                  const float* __restrict__ new_xyz, float* __restrict__ out)
{
    __shared__ float feat[NK * 68];
    __shared__ float red[4];

    const int tid = threadIdx.x;              // output channel o
    const int lane = tid & 31, wid = tid >> 5;

    float wr[68];
    wr[0] = w[tid * CIN + 0];
    wr[1] = w[tid * CIN + 1];
    wr[2] = w[tid * CIN + 2];
    wr[3] = 0.0f;
#pragma unroll
    for (int j = 0; j < NC; j++) wr[4 + j] = w[tid * CIN + 3 + j];
    const float bo = bias[tid], go = gamma[tid], be = beta[tid];

    const int k    = tid >> 2;   // 0..31 neighbor
    const int quad = tid & 3;    // 0..3

    for (int q = 0; q < QPB; q++) {
        const int gq = blockIdx.x * QPB + q;
        const int b  = gq >> 10;

        const int* ids = g_idx + (size_t)gq * NK;
        const int nidx = ids[k];
        const float4* vrow = (const float4*)(voxels + ((size_t)b * NN + nidx) * NC);
        float4* frow = (float4*)(feat + k * 68);
#pragma unroll
        for (int i = 0; i < 4; i++)
            frow[1 + quad * 4 + i] = vrow[quad * 4 + i];
        if (quad == 0) {
            const float* prow = xyz + ((size_t)b * NN + nidx) * 3;
            const float* qrow = new_xyz + (size_t)gq * 3;
            feat[k * 68 + 0] = __fsub_rn(prow[0], qrow[0]);
            feat[k * 68 + 1] = __fsub_rn(prow[1], qrow[1]);
            feat[k * 68 + 2] = __fsub_rn(prow[2], qrow[2]);
            feat[k * 68 + 3] = 0.0f;
        }
        __syncthreads();

        float m = -__int_as_float(0x7f800000);
#pragma unroll 4
        for (int kk = 0; kk < NK; kk++) {
            float acc = bo;
            const float4* f4 = (const float4*)(feat + kk * 68);
#pragma unroll
            for (int v = 0; v < 17; v++) {
                float4 f = f4[v];
                acc = fmaf(f.x, wr[4 * v + 0], acc);
                acc = fmaf(f.y, wr[4 * v + 1], acc);
                acc = fmaf(f.z, wr[4 * v + 2], acc);
                acc = fmaf(f.w, wr[4 * v + 3], acc);
            }
            m = fmaxf(m, acc);
        }

        // LayerNorm over 128 channels (one value per thread)
        float v = m;
#pragma unroll
        for (int off = 16; off; off >>= 1) v += __shfl_xor_sync(0xffffffffu, v, off);
        if (lane == 0) red[wid] = v;
        __syncthreads();
        const float mu = (red[0] + red[1] + red[2] + red[3]) * (1.0f / 128.0f);
        const float dm = m - mu;
        __syncthreads();
        float v2 = dm * dm;
#pragma unroll
        for (int off = 16; off; off >>= 1) v2 += __shfl_xor_sync(0xffffffffu, v2, off);
        if (lane == 0) red[wid] = v2;
        __syncthreads();
        const float var = (red[0] + red[1] + red[2] + red[3]) * (1.0f / 128.0f);
        const float y = dm * rsqrtf(var + 1e-5f) * go + be;
        out[(size_t)gq * NOUT + tid] = y;
        __syncthreads();   // protect feat/red for next query
    }
}

// ---------------------------------------------------------------------------
extern "C" void kernel_launch(void* const* d_in, const int* in_sizes, int n_in,
                              void* d_out, int out_size)
{
    const float* xyz    = (const float*)d_in[0];
    const float* voxels = (const float*)d_in[1];
    const float* conv_w = (const float*)d_in[2];
    const float* conv_b = (const float*)d_in[3];
    const float* ln_g   = (const float*)d_in[4];
    const float* ln_b   = (const float*)d_in[5];

    float* out      = (float*)d_out;                    // [B, S, OUT]
    float* new_xyz  = out + (size_t)NB * NS * NOUT;     // [B, S, 3]

    cudaFuncSetAttribute(fps_kernel, cudaFuncAttributeMaxDynamicSharedMemorySize,
                         3 * NN * sizeof(float));
    cudaFuncSetAttribute(knn_kernel, cudaFuncAttributeMaxDynamicSharedMemorySize,
                         NN * sizeof(float4));

    fps_kernel<<<NB, 1024, 3 * NN * sizeof(float)>>>(xyz, new_xyz);
    knn_kernel<<<NB * 8, 128, NN * sizeof(float4)>>>(xyz, new_xyz);
    embed_kernel<<<(NB * NS) / QPB, 128>>>(xyz, voxels, conv_w, conv_b,
                                           ln_g, ln_b, new_xyz, out);
}